// round 12
// baseline (speedup 1.0000x reference)
#include <cuda_runtime.h>
#include <cstddef>

#define LCH   4096
#define BATCH 4096
#define SEG   32
#define NSEG  128

// dynamic smem layout (bytes)
#define OFF_PP   0          // 16 KB: per-thread chunk prefix products PP[8]
#define OFF_OUT  16384      // 32 KB: output stage tile
#define OFF_NIB  49152      // 1 KB : obs nibbles
#define OFF_LUTP 50176      // 256 B
#define OFF_LUTQ 50432      // 256 B
#define OFF_WTOT 50688      // 128 B: warp totals (0-3 P, 4-7 Q)
#define SMEM_TOTAL 50816

struct Pots { float pd, po, pA0, pA1, pB0, pB1; };

__device__ __forceinline__ Pots make_pots(const float* jp, const float* bp) {
    Pots P;
    float j = jp[0], b0 = bp[0], b1 = bp[1];
    P.pd  = expf( 0.25f * j);
    P.po  = expf(-0.25f * j);
    P.pA0 = expf(-0.5f * b0);  P.pA1 = expf(0.5f * b0);
    P.pB0 = expf(-0.5f * b1);  P.pB1 = expf(0.5f * b1);
    return P;
}

// (max,*) 2x2 matrix product: C = A x B.  layout x=m00 y=m01 z=m10 w=m11
__device__ __forceinline__ float4 mm(float4 A, float4 B) {
    return make_float4(
        fmaxf(A.x * B.x, A.y * B.z), fmaxf(A.x * B.y, A.y * B.w),
        fmaxf(A.z * B.x, A.w * B.z), fmaxf(A.z * B.y, A.w * B.w));
}

__device__ __forceinline__ float4 shflup4(float4 v, int d) {
    v.x = __shfl_up_sync(0xffffffffu, v.x, d);
    v.y = __shfl_up_sync(0xffffffffu, v.y, d);
    v.z = __shfl_up_sync(0xffffffffu, v.z, d);
    v.w = __shfl_up_sync(0xffffffffu, v.w, d);
    return v;
}
__device__ __forceinline__ float4 shfldn4(float4 v, int d) {
    v.x = __shfl_down_sync(0xffffffffu, v.x, d);
    v.y = __shfl_down_sync(0xffffffffu, v.y, d);
    v.z = __shfl_down_sync(0xffffffffu, v.z, d);
    v.w = __shfl_down_sync(0xffffffffu, v.w, d);
    return v;
}

// ---------------------------------------------------------------------------
// R9 + forward-chain break: PP[g] prefix products stored in smem (per-thread
// private region) so all 8 chunks are independent in BOTH directions.
// ---------------------------------------------------------------------------
__global__ void __launch_bounds__(128, 4)
fused(const float* __restrict__ jp, const float* __restrict__ bp,
      const int* __restrict__ obs, float* __restrict__ out)
{
    extern __shared__ char dyn[];
    float4*        pp4   = reinterpret_cast<float4*>(dyn + OFF_PP);
    float4*        sm4   = reinterpret_cast<float4*>(dyn + OFF_OUT);
    unsigned char* smNib = reinterpret_cast<unsigned char*>(dyn + OFF_NIB);
    float4*        lutP  = reinterpret_cast<float4*>(dyn + OFF_LUTP);
    float4*        lutQ  = reinterpret_cast<float4*>(dyn + OFF_LUTQ);
    float4*        wTot  = reinterpret_cast<float4*>(dyn + OFF_WTOT);

    const int t = threadIdx.x, b = blockIdx.x;
    const int lane = t & 31, warp = t >> 5;

    const Pots pt = make_pots(jp, bp);

    // ---- obs -> nibbles (coalesced int4 loads) ----
    const int4* row4 = reinterpret_cast<const int4*>(obs + (size_t)b * LCH);
#pragma unroll
    for (int q = 0; q < 8; q++) {
        int  eq = q * 128 + t;
        int4 v  = row4[eq];
        smNib[eq] = (unsigned char)((v.x & 1) | ((v.y & 1) << 1) |
                                    ((v.z & 1) << 2) | ((v.w & 1) << 3));
    }

    // ---- 4-bit LUTs of 4-step transfer matrices ----
    if (t < 16) {
        float p00 = 1.f, p01 = 0.f, p10 = 0.f, p11 = 1.f;
        float q00 = 1.f, q01 = 0.f, q10 = 0.f, q11 = 1.f;
#pragma unroll
        for (int i = 0; i < 4; i++) {
            int   o  = (t >> i) & 1;
            float f0 = o ? pt.pB0 : pt.pA0;
            float f1 = o ? pt.pB1 : pt.pA1;
            float x0 = f0 * p00, x1 = f1 * p10, y0 = f0 * p01, y1 = f1 * p11;
            p00 = fmaxf(x0 * pt.pd, x1 * pt.po); p10 = fmaxf(x0 * pt.po, x1 * pt.pd);
            p01 = fmaxf(y0 * pt.pd, y1 * pt.po); p11 = fmaxf(y0 * pt.po, y1 * pt.pd);
            float a = f0 * fmaxf(q00 * pt.pd, q01 * pt.po);
            float c = f1 * fmaxf(q00 * pt.po, q01 * pt.pd);
            float d = f0 * fmaxf(q10 * pt.pd, q11 * pt.po);
            float e = f1 * fmaxf(q10 * pt.po, q11 * pt.pd);
            q00 = a; q01 = c; q10 = d; q11 = e;
        }
        lutP[t] = make_float4(p00, p01, p10, p11);
        lutQ[t] = make_float4(q00, q01, q10, q11);
    }
    __syncthreads();

    // ---- assemble 32-bit mask for segment t ----
    uint2 nb = reinterpret_cast<const uint2*>(smNib)[t];
    unsigned lo   = nb.x | (nb.x >> 4);
    unsigned lo16 = (lo & 0xFFu) | ((lo >> 8) & 0xFF00u);
    unsigned hi   = nb.y | (nb.y >> 4);
    unsigned hi16 = (hi & 0xFFu) | ((hi >> 8) & 0xFF00u);
    const unsigned bits = lo16 | (hi16 << 16);

    // ---- P compose with prefix products PP[g] -> smem (same-thread use) ----
    float4 P = make_float4(1.f, 0.f, 0.f, 1.f);
#pragma unroll
    for (int c = 0; c < 8; c++) {
        pp4[c * 128 + t] = P;            // PP[c] = chunk_{c-1} o ... o chunk_0
        P = mm(lutP[(bits >> (4 * c)) & 15u], P);
    }
    // P = full segment forward matrix

    // ---- Q compose with suffix products SS[g] in registers ----
    float4 SS[8];                 // SS[g] = chunkQ_{g+1} . ... . chunkQ_7 ; SS[7]=I
    float4 Q = make_float4(1.f, 0.f, 0.f, 1.f);
#pragma unroll
    for (int c = 7; c >= 0; c--) {
        SS[c] = Q;
        Q = mm(lutQ[(bits >> (4 * c)) & 15u], Q);
    }
    // Q = full segment backward matrix

    // ---- block scan: forward prefix of P, backward suffix of Q ----
    float4 sp = P;
#pragma unroll
    for (int d = 1; d < 32; d <<= 1) {
        float4 o = shflup4(sp, d);
        if (lane >= d) sp = mm(sp, o);
    }
    if (lane == 31) wTot[warp] = sp;

    float4 sq = Q;
#pragma unroll
    for (int d = 1; d < 32; d <<= 1) {
        float4 o = shfldn4(sq, d);
        if (lane + d < 32) sq = mm(sq, o);
    }
    if (lane == 0) wTot[4 + warp] = sq;
    __syncthreads();

    float4 prefP = make_float4(1.f, 0.f, 0.f, 1.f);
#pragma unroll
    for (int k = 2; k >= 0; k--)
        if (warp > k) prefP = mm(prefP, wTot[k]);

    float4 sufQ = make_float4(1.f, 0.f, 0.f, 1.f);
#pragma unroll
    for (int k = 1; k < 4; k++)
        if (warp < k) sufQ = mm(sufQ, wTot[4 + k]);

    float4 exP = shflup4(sp, 1);
    if (lane == 0) exP = make_float4(1.f, 0.f, 0.f, 1.f);
    exP = mm(exP, prefP);
    const float fs0 = fmaxf(exP.x, exP.y), fs1 = fmaxf(exP.z, exP.w); // fwd @ seg start

    float4 exQ = shfldn4(sq, 1);
    if (lane == 31) exQ = make_float4(1.f, 0.f, 0.f, 1.f);
    exQ = mm(exQ, sufQ);
    const float g0 = fmaxf(exQ.x, exQ.y), g1 = fmaxf(exQ.z, exQ.w);  // bwd @ seg end

    // ---- fused sweep: all 8 chunks independent in both directions ----
    const int xr = t & 7;
#pragma unroll
    for (int gg = 0; gg < 8; gg++) {
        // forward msg at chunk start from smem prefix product
        float4 PPg = pp4[gg * 128 + t];
        float f0 = fmaxf(PPg.x * fs0, PPg.y * fs1);
        float f1 = fmaxf(PPg.z * fs0, PPg.w * fs1);

        // backward msgs within chunk from suffix product (3 local steps)
        float bb0[4], bb1[4];
        bb0[3] = fmaxf(SS[gg].x * g0, SS[gg].y * g1);
        bb1[3] = fmaxf(SS[gg].z * g0, SS[gg].w * g1);
#pragma unroll
        for (int u = 2; u >= 0; u--) {
            int   i  = gg * 4 + u;
            int   o  = (bits >> (i + 1)) & 1;
            float p0 = o ? pt.pB0 : pt.pA0;
            float p1 = o ? pt.pB1 : pt.pA1;
            float y0 = p0 * bb0[u + 1];
            float y1 = p1 * bb1[u + 1];
            bb0[u] = fmaxf(y0 * pt.pd, y1 * pt.po);
            bb1[u] = fmaxf(y0 * pt.po, y1 * pt.pd);
        }

        float v0[4], v1[4];
#pragma unroll
        for (int u = 0; u < 4; u++) {
            int   i  = gg * 4 + u;
            int   o  = (bits >> i) & 1;
            float p0 = o ? pt.pB0 : pt.pA0;
            float p1 = o ? pt.pB1 : pt.pA1;
            float x0 = p0 * f0, x1 = p1 * f1;
            v0[u] = x0 * bb0[u];
            v1[u] = x1 * bb1[u];
            f0 = fmaxf(x0 * pt.pd, x1 * pt.po);
            f1 = fmaxf(x0 * pt.po, x1 * pt.pd);
        }
        sm4[(t * 8 + gg) ^ xr]        = make_float4(v0[0], v0[1], v0[2], v0[3]);
        sm4[(1024 + t * 8 + gg) ^ xr] = make_float4(v1[0], v1[1], v1[2], v1[3]);
    }
    __syncthreads();

    // ---- single LDS pass + fully-coalesced store: out[b][k][t] ----
    float4* out4 = reinterpret_cast<float4*>(out) + (size_t)b * 2048;
#pragma unroll
    for (int r = 0; r < 16; r++) {
        int w4 = r * 128 + t;
        int x  = (w4 >> 3) & 7;
        out4[w4] = sm4[w4 ^ x];
    }
}

// ---------------------------------------------------------------------------
extern "C" void kernel_launch(void* const* d_in, const int* in_sizes, int n_in,
                              void* d_out, int out_size)
{
    const float* jp  = nullptr;
    const float* bp  = nullptr;
    const int*   obs = nullptr;
    for (int i = 0; i < n_in; i++) {
        if (in_sizes[i] == 1)      jp  = (const float*)d_in[i];
        else if (in_sizes[i] == 2) bp  = (const float*)d_in[i];
        else                       obs = (const int*)d_in[i];
    }
    float* out = (float*)d_out;

    cudaFuncSetAttribute(fused, cudaFuncAttributeMaxDynamicSharedMemorySize, SMEM_TOTAL);
    fused<<<BATCH, 128, SMEM_TOTAL>>>(jp, bp, obs, out);
}